// round 13
// baseline (speedup 1.0000x reference)
#include <cuda_runtime.h>
#include <cuda_fp16.h>
#include <cstdint>

// Fixed problem shape: U=80000, I=40000, N=120000, K=64, L=3, E=1e6
#define KF 64
#define NN 120000
#define EMAX 1000000
#define FULLMASK 0xffffffffu

typedef unsigned long long ull;

// --------------------------- device scratch (no allocs allowed) -------------
__device__ __align__(16) __half g_h0[(size_t)(NN + 1) * KF];
__device__ __align__(16) __half g_h1[(size_t)(NN + 1) * KF];
__device__ __align__(16) __half g_wh[4 * 128 * 64];     // per-layer [W1;W2] fp16
__device__ int g_deg[NN];
__device__ int g_start[NN];
__device__ int g_pend[NN];
__device__ int g_cursor[NN];
__device__ int g_total;
__device__ __align__(16) int g_adj[2 * EMAX + 4 * NN];  // CSR padded to mult of 4

// =============================================================================
// init: e0 = l2norm(concat(Gu,Gi)) -> g_h0 (fp16) ; out[n] = rowsum/256
// also: zero pad row (w == Nn), reset g_total, zero degrees
// =============================================================================
__global__ __launch_bounds__(256) void init_kernel(
    const float* __restrict__ Gu, const float* __restrict__ Gi,
    float* __restrict__ out, int U, int Nn)
{
    int gt = blockIdx.x * blockDim.x + threadIdx.x;
    int w = gt >> 5;
    int lane = threadIdx.x & 31;
    if (gt == 0) g_total = 0;
    if (w > Nn) return;
    if (w == Nn) {
        __half2 z = __floats2half2_rn(0.f, 0.f);
        ((__half2*)(g_h0 + (size_t)Nn * KF))[lane] = z;
        ((__half2*)(g_h1 + (size_t)Nn * KF))[lane] = z;
        return;
    }
    const float* src = (w < U) ? (Gu + (size_t)w * KF) : (Gi + (size_t)(w - U) * KF);
    float2 v = ((const float2*)src)[lane];
    float ss = v.x * v.x + v.y * v.y;
    float sm = v.x + v.y;
#pragma unroll
    for (int off = 16; off >= 1; off >>= 1) {
        ss += __shfl_xor_sync(FULLMASK, ss, off);
        sm += __shfl_xor_sync(FULLMASK, sm, off);
    }
    float inv = 1.f / fmaxf(sqrtf(ss), 1e-12f);
    ((__half2*)(g_h0 + (size_t)w * KF))[lane] =
        __floats2half2_rn(v.x * inv, v.y * inv);
    if (lane == 0) { out[w] = sm * inv * (1.f / 256.f); g_deg[w] = 0; }
}

// =============================================================================
// weight convert: g_wh[l] = [[W1_l];[W2_l]] in fp16, row-major 128x64
// =============================================================================
__global__ __launch_bounds__(256) void wconv_kernel(
    const float* __restrict__ W1, const float* __restrict__ W2, int L)
{
    int i = blockIdx.x * 256 + threadIdx.x;
    if (i >= L * 4096) return;
    int l = i >> 12, rc = i & 4095;
    g_wh[l * 8192 + rc]        = __float2half_rn(W1[i]);
    g_wh[l * 8192 + 4096 + rc] = __float2half_rn(W2[i]);
}

// =============================================================================
// CSR build: histogram -> atomic block-scan assign (+pad) -> fill
// =============================================================================
__global__ __launch_bounds__(256) void hist_kernel(
    const int* __restrict__ eu, const int* __restrict__ ei, int E)
{
    int idx = blockIdx.x * blockDim.x + threadIdx.x;
    if (idx >= 2 * E) return;
    int dst = (idx < E) ? eu[idx] : ei[idx - E];
    atomicAdd(&g_deg[dst], 1);
}

// one kernel: per-block scan of padded degrees + one atomicAdd for the base.
// segment order across blocks is arbitrary (irrelevant for correctness).
__global__ __launch_bounds__(256) void assign_kernel(int Nn)
{
    int i = blockIdx.x * 256 + threadIdx.x;
    int d  = (i < Nn) ? g_deg[i] : 0;
    int pd = (d + 3) & ~3;
    int lane = threadIdx.x & 31, wid = threadIdx.x >> 5;
    int v = pd;
#pragma unroll
    for (int off = 1; off < 32; off <<= 1) {
        int t = __shfl_up_sync(FULLMASK, v, off);
        if (lane >= off) v += t;
    }
    __shared__ int wsum[8];
    __shared__ int sBase;
    if (lane == 31) wsum[wid] = v;
    __syncthreads();
    if (threadIdx.x < 8) {
        int wv = wsum[threadIdx.x];
#pragma unroll
        for (int off = 1; off < 8; off <<= 1) {
            int t = __shfl_up_sync(0xffu, wv, off);
            if ((int)threadIdx.x >= off) wv += t;
        }
        wsum[threadIdx.x] = wv;
    }
    __syncthreads();
    if (threadIdx.x == 0) sBase = atomicAdd(&g_total, wsum[7]);
    __syncthreads();
    if (i >= Nn) return;
    int woff = (wid > 0) ? wsum[wid - 1] : 0;
    int st = sBase + woff + v - pd;
    g_start[i]  = st;
    g_cursor[i] = st;
    g_pend[i]   = st + pd;
    for (int p = d; p < pd; ++p) g_adj[st + p] = Nn;   // zero-row pad
}

__global__ __launch_bounds__(256) void fill_kernel(
    const int* __restrict__ eu, const int* __restrict__ ei, int E)
{
    int idx = blockIdx.x * blockDim.x + threadIdx.x;
    if (idx >= 2 * E) return;
    int dst, src;
    if (idx < E) { dst = eu[idx]; src = ei[idx]; }
    else         { dst = ei[idx - E]; src = eu[idx - E]; }
    int pos = atomicAdd(&g_cursor[dst], 1);
    g_adj[pos] = src;
}

// =============================================================================
// fused layer (tensor-core, 128 nodes/block, gather inlined):
//   per node: side = sum_{nbr} x[nbr] (fp32 accum over fp16 rows), then
//   A = [s|p] fp16 -> mma.m16n8k16 against B = [W1;W2] -> bias, leaky,
//   l2norm, fp16 xout + out accumulation. 256 thr / 8 warps, 4 blocks/SM.
// =============================================================================
__device__ __forceinline__ uint32_t smem_u32(const void* p)
{
    return (uint32_t)__cvta_generic_to_shared(p);
}

__device__ __forceinline__ void ldsm_x4(uint32_t* r, uint32_t addr)
{
    asm volatile("ldmatrix.sync.aligned.m8n8.x4.shared.b16 {%0,%1,%2,%3}, [%4];"
                 : "=r"(r[0]), "=r"(r[1]), "=r"(r[2]), "=r"(r[3]) : "r"(addr));
}

__device__ __forceinline__ void ldsm_x4_t(uint32_t* r, uint32_t addr)
{
    asm volatile("ldmatrix.sync.aligned.m8n8.x4.trans.shared.b16 {%0,%1,%2,%3}, [%4];"
                 : "=r"(r[0]), "=r"(r[1]), "=r"(r[2]), "=r"(r[3]) : "r"(addr));
}

__device__ __forceinline__ void mma16816(float* d,
    uint32_t a0, uint32_t a1, uint32_t a2, uint32_t a3,
    uint32_t b0, uint32_t b1)
{
    asm volatile(
        "mma.sync.aligned.m16n8k16.row.col.f32.f16.f16.f32 "
        "{%0,%1,%2,%3}, {%4,%5,%6,%7}, {%8,%9}, {%0,%1,%2,%3};"
        : "+f"(d[0]), "+f"(d[1]), "+f"(d[2]), "+f"(d[3])
        : "r"(a0), "r"(a1), "r"(a2), "r"(a3), "r"(b0), "r"(b1));
}

#define APITCH 136   // halves per A row (272B; /4 = 68 ≡ 4 mod 32 -> LDSM clean)
#define BPITCH 72    // halves per B row (144B; /4 = 36 ≡ 4 mod 32 -> LDSM clean)
#define LNODES 128
// dynamic smem: sA 128*136*2 + sB 128*72*2 + sb 64*4 = 34816+18432+256 = 53504
#define LAYER_SMEM_BYTES (LNODES * APITCH * 2 + 128 * BPITCH * 2 + 256)

__global__ __launch_bounds__(256, 4) void layer_kernel(
    const __half* __restrict__ xin, __half* __restrict__ xout,
    const __half* __restrict__ Wh,
    const float* __restrict__ b1, const float* __restrict__ b2,
    float* __restrict__ out, int Nn)
{
    extern __shared__ __half smh[];
    __half* sA = smh;                       // 128 x APITCH
    __half* sB = smh + LNODES * APITCH;     // 128 x BPITCH
    float*  sb = (float*)(sB + 128 * BPITCH);

    int t = threadIdx.x, w = t >> 5, lane = t & 31;
    int base = blockIdx.x * LNODES;

    // ---- stage B: 128 rows x 64 halves (uint4 = 8 halves) ----
    const uint4* wsrc = (const uint4*)Wh;   // 1024 uint4
#pragma unroll
    for (int i = t; i < 1024; i += 256) {
        int r = i >> 3, c = i & 7;
        *(uint4*)(sB + r * BPITCH + c * 8) = wsrc[i];
    }
    if (t < 64) sb[t] = b1[t] + b2[t];

    // ---- fused gather + stage A: warp owns 16 nodes; lane owns k=2l,2l+1 ----
    const __half2* xh = (const __half2*)xin;
    for (int j = 0; j < 16; ++j) {
        int nl = w * 16 + j;
        int node = base + nl;
        __half2 s, p;
        if (node < Nn) {
            int a    = __ldg(g_start + node);
            int pend = __ldg(g_pend + node);
            float ax = 0.f, ay = 0.f;
            if (a < pend) {
                int4 A = *(const int4*)(g_adj + a);
                for (a += 4; a < pend; a += 4) {
                    int4 An = *(const int4*)(g_adj + a);
                    float2 v0 = __half22float2(__ldg(xh + (size_t)A.x * 32 + lane));
                    float2 v1 = __half22float2(__ldg(xh + (size_t)A.y * 32 + lane));
                    float2 v2 = __half22float2(__ldg(xh + (size_t)A.z * 32 + lane));
                    float2 v3 = __half22float2(__ldg(xh + (size_t)A.w * 32 + lane));
                    ax += (v0.x + v1.x) + (v2.x + v3.x);
                    ay += (v0.y + v1.y) + (v2.y + v3.y);
                    A = An;
                }
                float2 v0 = __half22float2(__ldg(xh + (size_t)A.x * 32 + lane));
                float2 v1 = __half22float2(__ldg(xh + (size_t)A.y * 32 + lane));
                float2 v2 = __half22float2(__ldg(xh + (size_t)A.z * 32 + lane));
                float2 v3 = __half22float2(__ldg(xh + (size_t)A.w * 32 + lane));
                ax += (v0.x + v1.x) + (v2.x + v3.x);
                ay += (v0.y + v1.y) + (v2.y + v3.y);
            }
            float2 xf = __half22float2(__ldg(xh + (size_t)node * 32 + lane));
            s = __floats2half2_rn(ax + xf.x, ay + xf.y);
            p = __floats2half2_rn(ax * xf.x, ay * xf.y);
        } else {
            s = __floats2half2_rn(0.f, 0.f);
            p = s;
        }
        *(__half2*)(sA + nl * APITCH + 2 * lane)      = s;
        *(__half2*)(sA + nl * APITCH + 64 + 2 * lane) = p;
    }
    __syncthreads();

    // ---- MMA mainloop: M=16 (per warp), N=64, K=128 ----
    int q = lane & 7, h = lane >> 3;
    uint32_t aAddr = smem_u32(sA) +
        (uint32_t)(((16 * w + ((h & 1) << 3) + q) * APITCH + ((h >> 1) << 3)) << 1);
    uint32_t bAddr = smem_u32(sB) +
        (uint32_t)(((q + ((h & 1) << 3)) * BPITCH + ((h >> 1) << 3)) << 1);

    float acc[8][4];
#pragma unroll
    for (int nt = 0; nt < 8; ++nt)
#pragma unroll
        for (int i = 0; i < 4; ++i) acc[nt][i] = 0.f;

#pragma unroll
    for (int ks = 0; ks < 8; ++ks) {
        uint32_t a[4];
        ldsm_x4(a, aAddr + ks * 32);                    // 16 k-cols = 32B
#pragma unroll
        for (int np = 0; np < 4; ++np) {
            uint32_t b[4];
            ldsm_x4_t(b, bAddr + ks * 16 * (BPITCH * 2) + np * 32);
            mma16816(acc[np * 2],     a[0], a[1], a[2], a[3], b[0], b[1]);
            mma16816(acc[np * 2 + 1], a[0], a[1], a[2], a[3], b[2], b[3]);
        }
    }

    // ---- epilogue: +bias, leaky, row l2norm (quad reduce), outputs ----
    int cb  = (lane & 3) * 2;        // col base within n-tile
    int rlo = lane >> 2;             // 0..7
    int node_lo = base + 16 * w + rlo;
    int node_hi = node_lo + 8;

    float ss_lo = 0.f, sm_lo = 0.f, ss_hi = 0.f, sm_hi = 0.f;
#pragma unroll
    for (int nt = 0; nt < 8; ++nt) {
        int col = nt * 8 + cb;
        float bb0 = sb[col], bb1 = sb[col + 1];
        float v0 = acc[nt][0] + bb0;
        float v1 = acc[nt][1] + bb1;
        float v2 = acc[nt][2] + bb0;
        float v3 = acc[nt][3] + bb1;
        v0 = v0 > 0.f ? v0 : 0.01f * v0;
        v1 = v1 > 0.f ? v1 : 0.01f * v1;
        v2 = v2 > 0.f ? v2 : 0.01f * v2;
        v3 = v3 > 0.f ? v3 : 0.01f * v3;
        acc[nt][0] = v0; acc[nt][1] = v1; acc[nt][2] = v2; acc[nt][3] = v3;
        ss_lo += v0 * v0 + v1 * v1;  sm_lo += v0 + v1;
        ss_hi += v2 * v2 + v3 * v3;  sm_hi += v2 + v3;
    }
#pragma unroll
    for (int off = 2; off >= 1; off >>= 1) {     // reduce over the quad
        ss_lo += __shfl_xor_sync(FULLMASK, ss_lo, off);
        sm_lo += __shfl_xor_sync(FULLMASK, sm_lo, off);
        ss_hi += __shfl_xor_sync(FULLMASK, ss_hi, off);
        sm_hi += __shfl_xor_sync(FULLMASK, sm_hi, off);
    }
    float inv_lo = 1.f / fmaxf(sqrtf(ss_lo), 1e-12f);
    float inv_hi = 1.f / fmaxf(sqrtf(ss_hi), 1e-12f);

    if (node_lo < Nn) {
        __half* xo = xout + (size_t)node_lo * KF;
#pragma unroll
        for (int nt = 0; nt < 8; ++nt)
            *(__half2*)(xo + nt * 8 + cb) =
                __floats2half2_rn(acc[nt][0] * inv_lo, acc[nt][1] * inv_lo);
        if ((lane & 3) == 0) out[node_lo] += sm_lo * inv_lo * (1.f / 256.f);
    }
    if (node_hi < Nn) {
        __half* xo = xout + (size_t)node_hi * KF;
#pragma unroll
        for (int nt = 0; nt < 8; ++nt)
            *(__half2*)(xo + nt * 8 + cb) =
                __floats2half2_rn(acc[nt][2] * inv_hi, acc[nt][3] * inv_hi);
        if ((lane & 3) == 0) out[node_hi] += sm_hi * inv_hi * (1.f / 256.f);
    }
}

// =============================================================================
// launch: init + wconv -> hist -> assign -> fill -> 3 x fused layer
// =============================================================================
extern "C" void kernel_launch(void* const* d_in, const int* in_sizes, int n_in,
                              void* d_out, int out_size)
{
    const float* Gu = (const float*)d_in[0];
    const float* Gi = (const float*)d_in[1];
    const float* W1 = (const float*)d_in[2];
    const float* b1 = (const float*)d_in[3];
    const float* W2 = (const float*)d_in[4];
    const float* b2 = (const float*)d_in[5];
    const int*   ed = (const int*)d_in[6];
    float* out = (float*)d_out;

    int U  = in_sizes[0] / KF;
    int I  = in_sizes[1] / KF;
    int Nn = U + I;
    int L  = in_sizes[3] / KF;
    int E  = in_sizes[6] / 2;
    int twoE = 2 * E;

    const int* eu = ed;
    const int* ei = ed + E;

    cudaFuncSetAttribute(layer_kernel,
                         cudaFuncAttributeMaxDynamicSharedMemorySize,
                         LAYER_SMEM_BYTES);

    __half *xa, *xb, *wh;
    cudaGetSymbolAddress((void**)&xa, g_h0);
    cudaGetSymbolAddress((void**)&xb, g_h1);
    cudaGetSymbolAddress((void**)&wh, g_wh);

    int initBlocks = ((Nn + 1) * 32 + 255) / 256;
    init_kernel<<<initBlocks, 256>>>(Gu, Gi, out, U, Nn);
    wconv_kernel<<<(L * 4096 + 255) / 256, 256>>>(W1, W2, L);

    int eBlocks = (twoE + 255) / 256;
    int nBlocks = (Nn + 255) / 256;
    hist_kernel<<<eBlocks, 256>>>(eu, ei, E);
    assign_kernel<<<nBlocks, 256>>>(Nn);
    fill_kernel<<<eBlocks, 256>>>(eu, ei, E);

    int lBlocks = (Nn + LNODES - 1) / LNODES;   // 938
    for (int l = 0; l < L; ++l) {
        layer_kernel<<<lBlocks, 256, LAYER_SMEM_BYTES>>>(
            xa, xb, wh + (size_t)l * 8192,
            b1 + (size_t)l * KF, b2 + (size_t)l * KF, out, Nn);
        __half* tmp = xa; xa = xb; xb = tmp;
    }
}

// round 14
// speedup vs baseline: 1.0063x; 1.0063x over previous
#include <cuda_runtime.h>
#include <cuda_fp16.h>
#include <cstdint>

// Fixed problem shape: U=80000, I=40000, N=120000, K=64, L=3, E=1e6
#define KF 64
#define NN 120000
#define EMAX 1000000
#define FULLMASK 0xffffffffu

typedef unsigned long long ull;

// --------------------------- device scratch (no allocs allowed) -------------
__device__ __align__(16) __half g_h0[(size_t)(NN + 1) * KF];
__device__ __align__(16) __half g_h1[(size_t)(NN + 1) * KF];
__device__ __align__(16) __half g_wh[4 * 128 * 64];     // per-layer [W1;W2] fp16
__device__ int g_deg[NN];
__device__ int g_start[NN];
__device__ int g_pend[NN];
__device__ int g_cursor[NN];
__device__ int g_total;
__device__ __align__(16) int g_adj[2 * EMAX + 4 * NN];  // CSR padded to mult of 4

// =============================================================================
// init: e0 = l2norm(concat(Gu,Gi)) -> g_h0 (fp16) ; out[n] = rowsum/256
// also: zero pad row (w == Nn), reset g_total, zero degrees
// =============================================================================
__global__ __launch_bounds__(256) void init_kernel(
    const float* __restrict__ Gu, const float* __restrict__ Gi,
    float* __restrict__ out, int U, int Nn)
{
    int gt = blockIdx.x * blockDim.x + threadIdx.x;
    int w = gt >> 5;
    int lane = threadIdx.x & 31;
    if (gt == 0) g_total = 0;
    if (w > Nn) return;
    if (w == Nn) {
        __half2 z = __floats2half2_rn(0.f, 0.f);
        ((__half2*)(g_h0 + (size_t)Nn * KF))[lane] = z;
        ((__half2*)(g_h1 + (size_t)Nn * KF))[lane] = z;
        return;
    }
    const float* src = (w < U) ? (Gu + (size_t)w * KF) : (Gi + (size_t)(w - U) * KF);
    float2 v = ((const float2*)src)[lane];
    float ss = v.x * v.x + v.y * v.y;
    float sm = v.x + v.y;
#pragma unroll
    for (int off = 16; off >= 1; off >>= 1) {
        ss += __shfl_xor_sync(FULLMASK, ss, off);
        sm += __shfl_xor_sync(FULLMASK, sm, off);
    }
    float inv = 1.f / fmaxf(sqrtf(ss), 1e-12f);
    ((__half2*)(g_h0 + (size_t)w * KF))[lane] =
        __floats2half2_rn(v.x * inv, v.y * inv);
    if (lane == 0) { out[w] = sm * inv * (1.f / 256.f); g_deg[w] = 0; }
}

// =============================================================================
// weight convert: g_wh[l] = [[W1_l];[W2_l]] in fp16, row-major 128x64
// =============================================================================
__global__ __launch_bounds__(256) void wconv_kernel(
    const float* __restrict__ W1, const float* __restrict__ W2, int L)
{
    int i = blockIdx.x * 256 + threadIdx.x;
    if (i >= L * 4096) return;
    int l = i >> 12, rc = i & 4095;
    g_wh[l * 8192 + rc]        = __float2half_rn(W1[i]);
    g_wh[l * 8192 + 4096 + rc] = __float2half_rn(W2[i]);
}

// =============================================================================
// CSR build: histogram -> atomic block-scan assign (+pad) -> fill
// =============================================================================
__global__ __launch_bounds__(256) void hist_kernel(
    const int* __restrict__ eu, const int* __restrict__ ei, int E)
{
    int idx = blockIdx.x * blockDim.x + threadIdx.x;
    if (idx >= 2 * E) return;
    int dst = (idx < E) ? eu[idx] : ei[idx - E];
    atomicAdd(&g_deg[dst], 1);
}

// one kernel: per-block scan of padded degrees + one atomicAdd for the base.
// segment order across blocks is arbitrary (irrelevant for correctness).
__global__ __launch_bounds__(256) void assign_kernel(int Nn)
{
    int i = blockIdx.x * 256 + threadIdx.x;
    int d  = (i < Nn) ? g_deg[i] : 0;
    int pd = (d + 3) & ~3;
    int lane = threadIdx.x & 31, wid = threadIdx.x >> 5;
    int v = pd;
#pragma unroll
    for (int off = 1; off < 32; off <<= 1) {
        int t = __shfl_up_sync(FULLMASK, v, off);
        if (lane >= off) v += t;
    }
    __shared__ int wsum[8];
    __shared__ int sBase;
    if (lane == 31) wsum[wid] = v;
    __syncthreads();
    if (threadIdx.x < 8) {
        int wv = wsum[threadIdx.x];
#pragma unroll
        for (int off = 1; off < 8; off <<= 1) {
            int t = __shfl_up_sync(0xffu, wv, off);
            if ((int)threadIdx.x >= off) wv += t;
        }
        wsum[threadIdx.x] = wv;
    }
    __syncthreads();
    if (threadIdx.x == 0) sBase = atomicAdd(&g_total, wsum[7]);
    __syncthreads();
    if (i >= Nn) return;
    int woff = (wid > 0) ? wsum[wid - 1] : 0;
    int st = sBase + woff + v - pd;
    g_start[i]  = st;
    g_cursor[i] = st;
    g_pend[i]   = st + pd;
    for (int p = d; p < pd; ++p) g_adj[st + p] = Nn;   // zero-row pad
}

__global__ __launch_bounds__(256) void fill_kernel(
    const int* __restrict__ eu, const int* __restrict__ ei, int E)
{
    int idx = blockIdx.x * blockDim.x + threadIdx.x;
    if (idx >= 2 * E) return;
    int dst, src;
    if (idx < E) { dst = eu[idx]; src = ei[idx]; }
    else         { dst = ei[idx - E]; src = eu[idx - E]; }
    int pos = atomicAdd(&g_cursor[dst], 1);
    g_adj[pos] = src;
}

// =============================================================================
// fused layer (tensor-core, 128 nodes/block, gather inlined):
//   per node: side = sum_{nbr} x[nbr] (fp32 accum over fp16 rows), then
//   A = [s|p] fp16 -> mma.m16n8k16 against B = [W1;W2] -> bias, leaky,
//   l2norm, fp16 xout + out accumulation. 256 thr / 8 warps, 4 blocks/SM.
// =============================================================================
__device__ __forceinline__ uint32_t smem_u32(const void* p)
{
    return (uint32_t)__cvta_generic_to_shared(p);
}

__device__ __forceinline__ void ldsm_x4(uint32_t* r, uint32_t addr)
{
    asm volatile("ldmatrix.sync.aligned.m8n8.x4.shared.b16 {%0,%1,%2,%3}, [%4];"
                 : "=r"(r[0]), "=r"(r[1]), "=r"(r[2]), "=r"(r[3]) : "r"(addr));
}

__device__ __forceinline__ void ldsm_x4_t(uint32_t* r, uint32_t addr)
{
    asm volatile("ldmatrix.sync.aligned.m8n8.x4.trans.shared.b16 {%0,%1,%2,%3}, [%4];"
                 : "=r"(r[0]), "=r"(r[1]), "=r"(r[2]), "=r"(r[3]) : "r"(addr));
}

__device__ __forceinline__ void mma16816(float* d,
    uint32_t a0, uint32_t a1, uint32_t a2, uint32_t a3,
    uint32_t b0, uint32_t b1)
{
    asm volatile(
        "mma.sync.aligned.m16n8k16.row.col.f32.f16.f16.f32 "
        "{%0,%1,%2,%3}, {%4,%5,%6,%7}, {%8,%9}, {%0,%1,%2,%3};"
        : "+f"(d[0]), "+f"(d[1]), "+f"(d[2]), "+f"(d[3])
        : "r"(a0), "r"(a1), "r"(a2), "r"(a3), "r"(b0), "r"(b1));
}

#define APITCH 136   // halves per A row (272B; /4 = 68 ≡ 4 mod 32 -> LDSM clean)
#define BPITCH 72    // halves per B row (144B; /4 = 36 ≡ 4 mod 32 -> LDSM clean)
#define LNODES 128
// dynamic smem: sA 128*136*2 + sB 128*72*2 + sb 64*4 = 34816+18432+256 = 53504
#define LAYER_SMEM_BYTES (LNODES * APITCH * 2 + 128 * BPITCH * 2 + 256)

__global__ __launch_bounds__(256, 4) void layer_kernel(
    const __half* __restrict__ xin, __half* __restrict__ xout,
    const __half* __restrict__ Wh,
    const float* __restrict__ b1, const float* __restrict__ b2,
    float* __restrict__ out, int Nn)
{
    extern __shared__ __half smh[];
    __half* sA = smh;                       // 128 x APITCH
    __half* sB = smh + LNODES * APITCH;     // 128 x BPITCH
    float*  sb = (float*)(sB + 128 * BPITCH);

    int t = threadIdx.x, w = t >> 5, lane = t & 31;
    int base = blockIdx.x * LNODES;

    // ---- stage B: 128 rows x 64 halves (uint4 = 8 halves) ----
    const uint4* wsrc = (const uint4*)Wh;   // 1024 uint4
#pragma unroll
    for (int i = t; i < 1024; i += 256) {
        int r = i >> 3, c = i & 7;
        *(uint4*)(sB + r * BPITCH + c * 8) = wsrc[i];
    }
    if (t < 64) sb[t] = b1[t] + b2[t];

    // ---- fused gather + stage A: warp owns 16 nodes; lane owns k=2l,2l+1 ----
    const __half2* xh = (const __half2*)xin;
    for (int j = 0; j < 16; ++j) {
        int nl = w * 16 + j;
        int node = base + nl;
        __half2 s, p;
        if (node < Nn) {
            int a    = __ldg(g_start + node);
            int pend = __ldg(g_pend + node);
            float ax = 0.f, ay = 0.f;
            if (a < pend) {
                int4 A = *(const int4*)(g_adj + a);
                for (a += 4; a < pend; a += 4) {
                    int4 An = *(const int4*)(g_adj + a);
                    float2 v0 = __half22float2(__ldg(xh + (size_t)A.x * 32 + lane));
                    float2 v1 = __half22float2(__ldg(xh + (size_t)A.y * 32 + lane));
                    float2 v2 = __half22float2(__ldg(xh + (size_t)A.z * 32 + lane));
                    float2 v3 = __half22float2(__ldg(xh + (size_t)A.w * 32 + lane));
                    ax += (v0.x + v1.x) + (v2.x + v3.x);
                    ay += (v0.y + v1.y) + (v2.y + v3.y);
                    A = An;
                }
                float2 v0 = __half22float2(__ldg(xh + (size_t)A.x * 32 + lane));
                float2 v1 = __half22float2(__ldg(xh + (size_t)A.y * 32 + lane));
                float2 v2 = __half22float2(__ldg(xh + (size_t)A.z * 32 + lane));
                float2 v3 = __half22float2(__ldg(xh + (size_t)A.w * 32 + lane));
                ax += (v0.x + v1.x) + (v2.x + v3.x);
                ay += (v0.y + v1.y) + (v2.y + v3.y);
            }
            float2 xf = __half22float2(__ldg(xh + (size_t)node * 32 + lane));
            s = __floats2half2_rn(ax + xf.x, ay + xf.y);
            p = __floats2half2_rn(ax * xf.x, ay * xf.y);
        } else {
            s = __floats2half2_rn(0.f, 0.f);
            p = s;
        }
        *(__half2*)(sA + nl * APITCH + 2 * lane)      = s;
        *(__half2*)(sA + nl * APITCH + 64 + 2 * lane) = p;
    }
    __syncthreads();

    // ---- MMA mainloop: M=16 (per warp), N=64, K=128 ----
    int q = lane & 7, h = lane >> 3;
    uint32_t aAddr = smem_u32(sA) +
        (uint32_t)(((16 * w + ((h & 1) << 3) + q) * APITCH + ((h >> 1) << 3)) << 1);
    uint32_t bAddr = smem_u32(sB) +
        (uint32_t)(((q + ((h & 1) << 3)) * BPITCH + ((h >> 1) << 3)) << 1);

    float acc[8][4];
#pragma unroll
    for (int nt = 0; nt < 8; ++nt)
#pragma unroll
        for (int i = 0; i < 4; ++i) acc[nt][i] = 0.f;

#pragma unroll
    for (int ks = 0; ks < 8; ++ks) {
        uint32_t a[4];
        ldsm_x4(a, aAddr + ks * 32);                    // 16 k-cols = 32B
#pragma unroll
        for (int np = 0; np < 4; ++np) {
            uint32_t b[4];
            ldsm_x4_t(b, bAddr + ks * 16 * (BPITCH * 2) + np * 32);
            mma16816(acc[np * 2],     a[0], a[1], a[2], a[3], b[0], b[1]);
            mma16816(acc[np * 2 + 1], a[0], a[1], a[2], a[3], b[2], b[3]);
        }
    }

    // ---- epilogue: +bias, leaky, row l2norm (quad reduce), outputs ----
    int cb  = (lane & 3) * 2;        // col base within n-tile
    int rlo = lane >> 2;             // 0..7
    int node_lo = base + 16 * w + rlo;
    int node_hi = node_lo + 8;

    float ss_lo = 0.f, sm_lo = 0.f, ss_hi = 0.f, sm_hi = 0.f;
#pragma unroll
    for (int nt = 0; nt < 8; ++nt) {
        int col = nt * 8 + cb;
        float bb0 = sb[col], bb1 = sb[col + 1];
        float v0 = acc[nt][0] + bb0;
        float v1 = acc[nt][1] + bb1;
        float v2 = acc[nt][2] + bb0;
        float v3 = acc[nt][3] + bb1;
        v0 = v0 > 0.f ? v0 : 0.01f * v0;
        v1 = v1 > 0.f ? v1 : 0.01f * v1;
        v2 = v2 > 0.f ? v2 : 0.01f * v2;
        v3 = v3 > 0.f ? v3 : 0.01f * v3;
        acc[nt][0] = v0; acc[nt][1] = v1; acc[nt][2] = v2; acc[nt][3] = v3;
        ss_lo += v0 * v0 + v1 * v1;  sm_lo += v0 + v1;
        ss_hi += v2 * v2 + v3 * v3;  sm_hi += v2 + v3;
    }
#pragma unroll
    for (int off = 2; off >= 1; off >>= 1) {     // reduce over the quad
        ss_lo += __shfl_xor_sync(FULLMASK, ss_lo, off);
        sm_lo += __shfl_xor_sync(FULLMASK, sm_lo, off);
        ss_hi += __shfl_xor_sync(FULLMASK, ss_hi, off);
        sm_hi += __shfl_xor_sync(FULLMASK, sm_hi, off);
    }
    float inv_lo = 1.f / fmaxf(sqrtf(ss_lo), 1e-12f);
    float inv_hi = 1.f / fmaxf(sqrtf(ss_hi), 1e-12f);

    if (node_lo < Nn) {
        __half* xo = xout + (size_t)node_lo * KF;
#pragma unroll
        for (int nt = 0; nt < 8; ++nt)
            *(__half2*)(xo + nt * 8 + cb) =
                __floats2half2_rn(acc[nt][0] * inv_lo, acc[nt][1] * inv_lo);
        if ((lane & 3) == 0) out[node_lo] += sm_lo * inv_lo * (1.f / 256.f);
    }
    if (node_hi < Nn) {
        __half* xo = xout + (size_t)node_hi * KF;
#pragma unroll
        for (int nt = 0; nt < 8; ++nt)
            *(__half2*)(xo + nt * 8 + cb) =
                __floats2half2_rn(acc[nt][2] * inv_hi, acc[nt][3] * inv_hi);
        if ((lane & 3) == 0) out[node_hi] += sm_hi * inv_hi * (1.f / 256.f);
    }
}

// =============================================================================
// launch: init + wconv -> hist -> assign -> fill -> 3 x fused layer
// =============================================================================
extern "C" void kernel_launch(void* const* d_in, const int* in_sizes, int n_in,
                              void* d_out, int out_size)
{
    const float* Gu = (const float*)d_in[0];
    const float* Gi = (const float*)d_in[1];
    const float* W1 = (const float*)d_in[2];
    const float* b1 = (const float*)d_in[3];
    const float* W2 = (const float*)d_in[4];
    const float* b2 = (const float*)d_in[5];
    const int*   ed = (const int*)d_in[6];
    float* out = (float*)d_out;

    int U  = in_sizes[0] / KF;
    int I  = in_sizes[1] / KF;
    int Nn = U + I;
    int L  = in_sizes[3] / KF;
    int E  = in_sizes[6] / 2;
    int twoE = 2 * E;

    const int* eu = ed;
    const int* ei = ed + E;

    cudaFuncSetAttribute(layer_kernel,
                         cudaFuncAttributeMaxDynamicSharedMemorySize,
                         LAYER_SMEM_BYTES);

    __half *xa, *xb, *wh;
    cudaGetSymbolAddress((void**)&xa, g_h0);
    cudaGetSymbolAddress((void**)&xb, g_h1);
    cudaGetSymbolAddress((void**)&wh, g_wh);

    int initBlocks = ((Nn + 1) * 32 + 255) / 256;
    init_kernel<<<initBlocks, 256>>>(Gu, Gi, out, U, Nn);
    wconv_kernel<<<(L * 4096 + 255) / 256, 256>>>(W1, W2, L);

    int eBlocks = (twoE + 255) / 256;
    int nBlocks = (Nn + 255) / 256;
    hist_kernel<<<eBlocks, 256>>>(eu, ei, E);
    assign_kernel<<<nBlocks, 256>>>(Nn);
    fill_kernel<<<eBlocks, 256>>>(eu, ei, E);

    int lBlocks = (Nn + LNODES - 1) / LNODES;   // 938
    for (int l = 0; l < L; ++l) {
        layer_kernel<<<lBlocks, 256, LAYER_SMEM_BYTES>>>(
            xa, xb, wh + (size_t)l * 8192,
            b1 + (size_t)l * KF, b2 + (size_t)l * KF, out, Nn);
        __half* tmp = xa; xa = xb; xb = tmp;
    }
}

// round 15
// speedup vs baseline: 1.2036x; 1.1961x over previous
#include <cuda_runtime.h>
#include <cuda_fp16.h>
#include <cstdint>

// Fixed problem shape: U=80000, I=40000, N=120000, K=64, L=3, E=1e6
#define KF 64
#define NN 120000
#define EMAX 1000000
#define FULLMASK 0xffffffffu

typedef unsigned long long ull;

// --------------------------- device scratch (no allocs allowed) -------------
__device__ __align__(16) __half g_h0[(size_t)(NN + 1) * KF];
__device__ __align__(16) __half g_h1[(size_t)(NN + 1) * KF];
__device__ __align__(16) __half g_side[(size_t)NN * KF];
__device__ __align__(16) __half g_wh[4 * 128 * 64];     // per-layer [W1;W2] fp16
__device__ int g_deg[NN];
__device__ int g_start[NN];
__device__ int g_pend[NN];
__device__ int g_cursor[NN];
__device__ int g_total;
__device__ __align__(16) int g_adj[2 * EMAX + 4 * NN];  // CSR padded to mult of 4

// =============================================================================
// init: e0 = l2norm(concat(Gu,Gi)) -> g_h0 (fp16) ; out[n] = rowsum/256
// also: zero pad row (w == Nn), reset g_total, zero degrees
// =============================================================================
__global__ __launch_bounds__(256) void init_kernel(
    const float* __restrict__ Gu, const float* __restrict__ Gi,
    float* __restrict__ out, int U, int Nn)
{
    int gt = blockIdx.x * blockDim.x + threadIdx.x;
    int w = gt >> 5;
    int lane = threadIdx.x & 31;
    if (gt == 0) g_total = 0;
    if (w > Nn) return;
    if (w == Nn) {
        __half2 z = __floats2half2_rn(0.f, 0.f);
        ((__half2*)(g_h0 + (size_t)Nn * KF))[lane] = z;
        ((__half2*)(g_h1 + (size_t)Nn * KF))[lane] = z;
        return;
    }
    const float* src = (w < U) ? (Gu + (size_t)w * KF) : (Gi + (size_t)(w - U) * KF);
    float2 v = ((const float2*)src)[lane];
    float ss = v.x * v.x + v.y * v.y;
    float sm = v.x + v.y;
#pragma unroll
    for (int off = 16; off >= 1; off >>= 1) {
        ss += __shfl_xor_sync(FULLMASK, ss, off);
        sm += __shfl_xor_sync(FULLMASK, sm, off);
    }
    float inv = 1.f / fmaxf(sqrtf(ss), 1e-12f);
    ((__half2*)(g_h0 + (size_t)w * KF))[lane] =
        __floats2half2_rn(v.x * inv, v.y * inv);
    if (lane == 0) { out[w] = sm * inv * (1.f / 256.f); g_deg[w] = 0; }
}

// =============================================================================
// weight convert: g_wh[l] = [[W1_l];[W2_l]] in fp16, row-major 128x64
// =============================================================================
__global__ __launch_bounds__(256) void wconv_kernel(
    const float* __restrict__ W1, const float* __restrict__ W2, int L)
{
    int i = blockIdx.x * 256 + threadIdx.x;
    if (i >= L * 4096) return;
    int l = i >> 12, rc = i & 4095;
    g_wh[l * 8192 + rc]        = __float2half_rn(W1[i]);
    g_wh[l * 8192 + 4096 + rc] = __float2half_rn(W2[i]);
}

// =============================================================================
// CSR build: histogram -> atomic block-scan assign (+pad) -> fill
// =============================================================================
__global__ __launch_bounds__(256) void hist_kernel(
    const int* __restrict__ eu, const int* __restrict__ ei, int E)
{
    int idx = blockIdx.x * blockDim.x + threadIdx.x;
    if (idx >= 2 * E) return;
    int dst = (idx < E) ? eu[idx] : ei[idx - E];
    atomicAdd(&g_deg[dst], 1);
}

// per-block scan of padded degrees + one atomicAdd for the base.
// segment order across blocks is arbitrary (irrelevant for correctness).
__global__ __launch_bounds__(256) void assign_kernel(int Nn)
{
    int i = blockIdx.x * 256 + threadIdx.x;
    int d  = (i < Nn) ? g_deg[i] : 0;
    int pd = (d + 3) & ~3;
    int lane = threadIdx.x & 31, wid = threadIdx.x >> 5;
    int v = pd;
#pragma unroll
    for (int off = 1; off < 32; off <<= 1) {
        int t = __shfl_up_sync(FULLMASK, v, off);
        if (lane >= off) v += t;
    }
    __shared__ int wsum[8];
    __shared__ int sBase;
    if (lane == 31) wsum[wid] = v;
    __syncthreads();
    if (threadIdx.x < 8) {
        int wv = wsum[threadIdx.x];
#pragma unroll
        for (int off = 1; off < 8; off <<= 1) {
            int t = __shfl_up_sync(0xffu, wv, off);
            if ((int)threadIdx.x >= off) wv += t;
        }
        wsum[threadIdx.x] = wv;
    }
    __syncthreads();
    if (threadIdx.x == 0) sBase = atomicAdd(&g_total, wsum[7]);
    __syncthreads();
    if (i >= Nn) return;
    int woff = (wid > 0) ? wsum[wid - 1] : 0;
    int st = sBase + woff + v - pd;
    g_start[i]  = st;
    g_cursor[i] = st;
    g_pend[i]   = st + pd;
    for (int p = d; p < pd; ++p) g_adj[st + p] = Nn;   // zero-row pad
}

__global__ __launch_bounds__(256) void fill_kernel(
    const int* __restrict__ eu, const int* __restrict__ ei, int E)
{
    int idx = blockIdx.x * blockDim.x + threadIdx.x;
    if (idx >= 2 * E) return;
    int dst, src;
    if (idx < E) { dst = eu[idx]; src = ei[idx]; }
    else         { dst = ei[idx - E]; src = eu[idx - E]; }
    int pos = atomicAdd(&g_cursor[dst], 1);
    g_adj[pos] = src;
}

// =============================================================================
// gather: side = A @ x (x fp16, accumulate fp32, store fp16). Warp per node.
// High occupancy standalone kernel -> cross-warp latency overlap.
// =============================================================================
__global__ __launch_bounds__(256) void gather_kernel(
    const __half* __restrict__ xin, int Nn)
{
    int node = (blockIdx.x * blockDim.x + threadIdx.x) >> 5;
    if (node >= Nn) return;
    int lane = threadIdx.x & 31;
    const __half2* xh = (const __half2*)xin;

    int a    = __ldg(g_start + node);
    int pend = __ldg(g_pend + node);
    float ax = 0.f, ay = 0.f;
    if (a < pend) {
        int4 A = *(const int4*)(g_adj + a);
        for (a += 4; a < pend; a += 4) {
            int4 An = *(const int4*)(g_adj + a);
            float2 v0 = __half22float2(__ldg(xh + (size_t)A.x * 32 + lane));
            float2 v1 = __half22float2(__ldg(xh + (size_t)A.y * 32 + lane));
            float2 v2 = __half22float2(__ldg(xh + (size_t)A.z * 32 + lane));
            float2 v3 = __half22float2(__ldg(xh + (size_t)A.w * 32 + lane));
            ax += (v0.x + v1.x) + (v2.x + v3.x);
            ay += (v0.y + v1.y) + (v2.y + v3.y);
            A = An;
        }
        float2 v0 = __half22float2(__ldg(xh + (size_t)A.x * 32 + lane));
        float2 v1 = __half22float2(__ldg(xh + (size_t)A.y * 32 + lane));
        float2 v2 = __half22float2(__ldg(xh + (size_t)A.z * 32 + lane));
        float2 v3 = __half22float2(__ldg(xh + (size_t)A.w * 32 + lane));
        ax += (v0.x + v1.x) + (v2.x + v3.x);
        ay += (v0.y + v1.y) + (v2.y + v3.y);
    }
    ((__half2*)(g_side + (size_t)node * KF))[lane] = __floats2half2_rn(ax, ay);
}

// =============================================================================
// layer (tensor-core, 128 nodes/block): A = [s|p] (128x128 fp16),
// B = [W1;W2] (128x64 fp16), C = A@B fp32 via mma.m16n8k16.
// 256 threads = 8 warps; warp w owns rows 16w..16w+15. Dynamic smem 53.5KB.
// =============================================================================
__device__ __forceinline__ uint32_t smem_u32(const void* p)
{
    return (uint32_t)__cvta_generic_to_shared(p);
}

__device__ __forceinline__ void ldsm_x4(uint32_t* r, uint32_t addr)
{
    asm volatile("ldmatrix.sync.aligned.m8n8.x4.shared.b16 {%0,%1,%2,%3}, [%4];"
                 : "=r"(r[0]), "=r"(r[1]), "=r"(r[2]), "=r"(r[3]) : "r"(addr));
}

__device__ __forceinline__ void ldsm_x4_t(uint32_t* r, uint32_t addr)
{
    asm volatile("ldmatrix.sync.aligned.m8n8.x4.trans.shared.b16 {%0,%1,%2,%3}, [%4];"
                 : "=r"(r[0]), "=r"(r[1]), "=r"(r[2]), "=r"(r[3]) : "r"(addr));
}

__device__ __forceinline__ void mma16816(float* d,
    uint32_t a0, uint32_t a1, uint32_t a2, uint32_t a3,
    uint32_t b0, uint32_t b1)
{
    asm volatile(
        "mma.sync.aligned.m16n8k16.row.col.f32.f16.f16.f32 "
        "{%0,%1,%2,%3}, {%4,%5,%6,%7}, {%8,%9}, {%0,%1,%2,%3};"
        : "+f"(d[0]), "+f"(d[1]), "+f"(d[2]), "+f"(d[3])
        : "r"(a0), "r"(a1), "r"(a2), "r"(a3), "r"(b0), "r"(b1));
}

#define APITCH 136   // halves per A row (272B; /4 = 68 ≡ 4 mod 32 -> LDSM clean)
#define BPITCH 72    // halves per B row (144B; /4 = 36 ≡ 4 mod 32 -> LDSM clean)
#define LNODES 128
// dynamic smem: sA 128*136*2 + sB 128*72*2 + sb 64*4 = 34816+18432+256 = 53504
#define LAYER_SMEM_BYTES (LNODES * APITCH * 2 + 128 * BPITCH * 2 + 256)

__global__ __launch_bounds__(256, 4) void layer_kernel(
    const __half* __restrict__ xin, __half* __restrict__ xout,
    const __half* __restrict__ Wh,
    const float* __restrict__ b1, const float* __restrict__ b2,
    float* __restrict__ out, int Nn)
{
    extern __shared__ __half smh[];
    __half* sA = smh;                       // 128 x APITCH
    __half* sB = smh + LNODES * APITCH;     // 128 x BPITCH
    float*  sb = (float*)(sB + 128 * BPITCH);

    int t = threadIdx.x, w = t >> 5, lane = t & 31;
    int base = blockIdx.x * LNODES;

    // ---- stage B: 128 rows x 64 halves (uint4 = 8 halves) ----
    const uint4* wsrc = (const uint4*)Wh;   // 1024 uint4
#pragma unroll
    for (int i = t; i < 1024; i += 256) {
        int r = i >> 3, c = i & 7;
        *(uint4*)(sB + r * BPITCH + c * 8) = wsrc[i];
    }
    if (t < 64) sb[t] = b1[t] + b2[t];

    // ---- stage A: warp handles 16 nodes; lane owns k = 2*lane, 2*lane+1 ----
    const __half2* xh   = (const __half2*)xin;
    const __half2* sd2  = (const __half2*)g_side;
#pragma unroll 4
    for (int j = 0; j < 16; ++j) {
        int nl = w * 16 + j;
        int node = base + nl;
        __half2 s, p;
        if (node < Nn) {
            __half2 sv = __ldg(sd2 + (size_t)node * 32 + lane);
            __half2 xv = __ldg(xh  + (size_t)node * 32 + lane);
            s = __hadd2(sv, xv);
            p = __hmul2(sv, xv);
        } else {
            s = __floats2half2_rn(0.f, 0.f);
            p = s;
        }
        *(__half2*)(sA + nl * APITCH + 2 * lane)      = s;
        *(__half2*)(sA + nl * APITCH + 64 + 2 * lane) = p;
    }
    __syncthreads();

    // ---- MMA mainloop: M=16 (per warp), N=64, K=128 ----
    int q = lane & 7, h = lane >> 3;
    uint32_t aAddr = smem_u32(sA) +
        (uint32_t)(((16 * w + ((h & 1) << 3) + q) * APITCH + ((h >> 1) << 3)) << 1);
    uint32_t bAddr = smem_u32(sB) +
        (uint32_t)(((q + ((h & 1) << 3)) * BPITCH + ((h >> 1) << 3)) << 1);

    float acc[8][4];
#pragma unroll
    for (int nt = 0; nt < 8; ++nt)
#pragma unroll
        for (int i = 0; i < 4; ++i) acc[nt][i] = 0.f;

#pragma unroll
    for (int ks = 0; ks < 8; ++ks) {
        uint32_t a[4];
        ldsm_x4(a, aAddr + ks * 32);                    // 16 k-cols = 32B
#pragma unroll
        for (int np = 0; np < 4; ++np) {
            uint32_t b[4];
            ldsm_x4_t(b, bAddr + ks * 16 * (BPITCH * 2) + np * 32);
            mma16816(acc[np * 2],     a[0], a[1], a[2], a[3], b[0], b[1]);
            mma16816(acc[np * 2 + 1], a[0], a[1], a[2], a[3], b[2], b[3]);
        }
    }

    // ---- epilogue: +bias, leaky, row l2norm (quad reduce), outputs ----
    int cb  = (lane & 3) * 2;        // col base within n-tile
    int rlo = lane >> 2;             // 0..7
    int node_lo = base + 16 * w + rlo;
    int node_hi = node_lo + 8;

    float ss_lo = 0.f, sm_lo = 0.f, ss_hi = 0.f, sm_hi = 0.f;
#pragma unroll
    for (int nt = 0; nt < 8; ++nt) {
        int col = nt * 8 + cb;
        float bb0 = sb[col], bb1 = sb[col + 1];
        float v0 = acc[nt][0] + bb0;
        float v1 = acc[nt][1] + bb1;
        float v2 = acc[nt][2] + bb0;
        float v3 = acc[nt][3] + bb1;
        v0 = v0 > 0.f ? v0 : 0.01f * v0;
        v1 = v1 > 0.f ? v1 : 0.01f * v1;
        v2 = v2 > 0.f ? v2 : 0.01f * v2;
        v3 = v3 > 0.f ? v3 : 0.01f * v3;
        acc[nt][0] = v0; acc[nt][1] = v1; acc[nt][2] = v2; acc[nt][3] = v3;
        ss_lo += v0 * v0 + v1 * v1;  sm_lo += v0 + v1;
        ss_hi += v2 * v2 + v3 * v3;  sm_hi += v2 + v3;
    }
#pragma unroll
    for (int off = 2; off >= 1; off >>= 1) {     // reduce over the quad
        ss_lo += __shfl_xor_sync(FULLMASK, ss_lo, off);
        sm_lo += __shfl_xor_sync(FULLMASK, sm_lo, off);
        ss_hi += __shfl_xor_sync(FULLMASK, ss_hi, off);
        sm_hi += __shfl_xor_sync(FULLMASK, sm_hi, off);
    }
    float inv_lo = 1.f / fmaxf(sqrtf(ss_lo), 1e-12f);
    float inv_hi = 1.f / fmaxf(sqrtf(ss_hi), 1e-12f);

    if (node_lo < Nn) {
        __half* xo = xout + (size_t)node_lo * KF;
#pragma unroll
        for (int nt = 0; nt < 8; ++nt)
            *(__half2*)(xo + nt * 8 + cb) =
                __floats2half2_rn(acc[nt][0] * inv_lo, acc[nt][1] * inv_lo);
        if ((lane & 3) == 0) out[node_lo] += sm_lo * inv_lo * (1.f / 256.f);
    }
    if (node_hi < Nn) {
        __half* xo = xout + (size_t)node_hi * KF;
#pragma unroll
        for (int nt = 0; nt < 8; ++nt)
            *(__half2*)(xo + nt * 8 + cb) =
                __floats2half2_rn(acc[nt][2] * inv_hi, acc[nt][3] * inv_hi);
        if ((lane & 3) == 0) out[node_hi] += sm_hi * inv_hi * (1.f / 256.f);
    }
}

// =============================================================================
// launch: init + wconv -> hist -> assign -> fill -> 3 x (gather -> layer)
// =============================================================================
extern "C" void kernel_launch(void* const* d_in, const int* in_sizes, int n_in,
                              void* d_out, int out_size)
{
    const float* Gu = (const float*)d_in[0];
    const float* Gi = (const float*)d_in[1];
    const float* W1 = (const float*)d_in[2];
    const float* b1 = (const float*)d_in[3];
    const float* W2 = (const float*)d_in[4];
    const float* b2 = (const float*)d_in[5];
    const int*   ed = (const int*)d_in[6];
    float* out = (float*)d_out;

    int U  = in_sizes[0] / KF;
    int I  = in_sizes[1] / KF;
    int Nn = U + I;
    int L  = in_sizes[3] / KF;
    int E  = in_sizes[6] / 2;
    int twoE = 2 * E;

    const int* eu = ed;
    const int* ei = ed + E;

    cudaFuncSetAttribute(layer_kernel,
                         cudaFuncAttributeMaxDynamicSharedMemorySize,
                         LAYER_SMEM_BYTES);

    __half *xa, *xb, *wh;
    cudaGetSymbolAddress((void**)&xa, g_h0);
    cudaGetSymbolAddress((void**)&xb, g_h1);
    cudaGetSymbolAddress((void**)&wh, g_wh);

    int initBlocks = ((Nn + 1) * 32 + 255) / 256;
    init_kernel<<<initBlocks, 256>>>(Gu, Gi, out, U, Nn);
    wconv_kernel<<<(L * 4096 + 255) / 256, 256>>>(W1, W2, L);

    int eBlocks = (twoE + 255) / 256;
    int nBlocks = (Nn + 255) / 256;
    hist_kernel<<<eBlocks, 256>>>(eu, ei, E);
    assign_kernel<<<nBlocks, 256>>>(Nn);
    fill_kernel<<<eBlocks, 256>>>(eu, ei, E);

    int gBlocks = (Nn * 32 + 255) / 256;
    int lBlocks = (Nn + LNODES - 1) / LNODES;   // 938
    for (int l = 0; l < L; ++l) {
        gather_kernel<<<gBlocks, 256>>>(xa, Nn);
        layer_kernel<<<lBlocks, 256, LAYER_SMEM_BYTES>>>(
            xa, xb, wh + (size_t)l * 8192,
            b1 + (size_t)l * KF, b2 + (size_t)l * KF, out, Nn);
        __half* tmp = xa; xa = xb; xb = tmp;
    }
}